// round 11
// baseline (speedup 1.0000x reference)
#include <cuda_runtime.h>
#include <cuda_bf16.h>
#include <cstdint>

#define FULL 0xffffffffu

static constexpr int NN      = 50000;
static constexpr int NE      = 400000;
static constexpr int NODE_IN = 128;
static constexpr int F       = 256;   // HEADS*HID
static constexpr int HEADS   = 8;
static constexpr float SLOPE = 0.2f;
static constexpr int MPAD    = 50048; // 391 * 128

// ---------------- scratch (device globals; no allocation allowed) ----------------
__device__ float g_h[(size_t)NN * F];   // pre-aggregation node features
__device__ float g_P[(size_t)NN * 64];  // per-node predictor partials [Pa|Pb]
__device__ __nv_bfloat16 g_Ah[(size_t)MPAD * 256];
__device__ __nv_bfloat16 g_Al[(size_t)MPAD * 256];
__device__ __nv_bfloat16 g_Bh[256 * 256];
__device__ __nv_bfloat16 g_Bl[256 * 256];
__device__ float g_as[NN * HEADS];
__device__ float g_ad[NN * HEADS];
__device__ int   g_deg[NN];
__device__ int   g_off[NN + 1];
__device__ int   g_cur[NN];
__device__ int   g_col[NE];

__device__ __forceinline__ float lrelu(float x) { return x > 0.f ? x : SLOPE * x; }

__device__ __forceinline__ uint32_t smem_u32(const void* p) {
    uint32_t a;
    asm("{ .reg .u64 t; cvta.to.shared.u64 t, %1; cvt.u32.u64 %0, t; }" : "=r"(a) : "l"(p));
    return a;
}
__device__ __forceinline__ void ldsm4(uint32_t* r, uint32_t addr) {
    asm volatile("ldmatrix.sync.aligned.m8n8.x4.shared.b16 {%0,%1,%2,%3}, [%4];"
                 : "=r"(r[0]), "=r"(r[1]), "=r"(r[2]), "=r"(r[3]) : "r"(addr));
}
__device__ __forceinline__ void mma16816(float* c, const uint32_t* a, const uint32_t* b) {
    asm volatile("mma.sync.aligned.m16n8k16.row.col.f32.bf16.bf16.f32 "
                 "{%0,%1,%2,%3}, {%4,%5,%6,%7}, {%8,%9}, {%0,%1,%2,%3};"
                 : "+f"(c[0]), "+f"(c[1]), "+f"(c[2]), "+f"(c[3])
                 : "r"(a[0]), "r"(a[1]), "r"(a[2]), "r"(a[3]), "r"(b[0]), "r"(b[1]));
}
// packed c = a*b + c  (FFMA2; sm_100+)
__device__ __forceinline__ void ffma2(float2& c, float2 a, float2 b) {
    unsigned long long cc, aa, bb;
    cc = *reinterpret_cast<unsigned long long*>(&c);
    aa = *reinterpret_cast<unsigned long long*>(&a);
    bb = *reinterpret_cast<unsigned long long*>(&b);
    asm("fma.rn.f32x2 %0, %1, %2, %0;" : "+l"(cc) : "l"(aa), "l"(bb));
    *reinterpret_cast<unsigned long long*>(&c) = cc;
}
__device__ __forceinline__ void cpasync16(void* dst, const void* src) {
    asm volatile("cp.async.ca.shared.global [%0], [%1], 16;"
                 :: "r"(smem_u32(dst)), "l"(src));
}

// ---------------- CSR build ----------------
__global__ void k_zero(int* p, int n) {
    int i = blockIdx.x * blockDim.x + threadIdx.x;
    if (i < n) p[i] = 0;
}
__global__ void k_count(const int* __restrict__ ei) {
    int e = blockIdx.x * blockDim.x + threadIdx.x;
    if (e < NE) atomicAdd(&g_deg[ei[NE + e]], 1);
}
__global__ void k_scan() {
    __shared__ int sh[32];
    __shared__ int s_carry;
    int tid = threadIdx.x;
    if (tid == 0) s_carry = 0;
    __syncthreads();
    for (int base = 0; base < NN; base += 1024) {
        int v = (base + tid < NN) ? g_deg[base + tid] : 0;
        int x = v;
        #pragma unroll
        for (int d = 1; d < 32; d <<= 1) {
            int y = __shfl_up_sync(FULL, x, d);
            if ((tid & 31) >= d) x += y;
        }
        if ((tid & 31) == 31) sh[tid >> 5] = x;
        __syncthreads();
        if (tid < 32) {
            int w = sh[tid];
            int wx = w;
            #pragma unroll
            for (int d = 1; d < 32; d <<= 1) {
                int y = __shfl_up_sync(FULL, wx, d);
                if (tid >= d) wx += y;
            }
            sh[tid] = wx - w;
        }
        __syncthreads();
        int incl = x + sh[tid >> 5];
        int excl = incl - v;
        int carry = s_carry;
        if (base + tid < NN) {
            g_off[base + tid] = carry + excl;
            g_cur[base + tid] = carry + excl;
        }
        __syncthreads();
        if (tid == 1023) s_carry = carry + incl;
        __syncthreads();
    }
    if (tid == 0) g_off[NN] = s_carry;
}
__global__ void k_fill(const int* __restrict__ ei) {
    int e = blockIdx.x * blockDim.x + threadIdx.x;
    if (e < NE) {
        int s = ei[e], d = ei[NE + e];
        int p = atomicAdd(&g_cur[d], 1);
        g_col[p] = s;
    }
}

// ---------------- precision-split conversions ----------------
__global__ void k_splitA(const float* __restrict__ A, int total4) {
    int i = blockIdx.x * blockDim.x + threadIdx.x;
    if (i >= total4) return;
    float4 v = ((const float4*)A)[i];
    ushort4 h, l;
    float f;
    __nv_bfloat16 b;
    b = __float2bfloat16_rn(v.x); f = v.x - __bfloat162float(b); h.x = __bfloat16_as_ushort(b); l.x = __bfloat16_as_ushort(__float2bfloat16_rn(f));
    b = __float2bfloat16_rn(v.y); f = v.y - __bfloat162float(b); h.y = __bfloat16_as_ushort(b); l.y = __bfloat16_as_ushort(__float2bfloat16_rn(f));
    b = __float2bfloat16_rn(v.z); f = v.z - __bfloat162float(b); h.z = __bfloat16_as_ushort(b); l.z = __bfloat16_as_ushort(__float2bfloat16_rn(f));
    b = __float2bfloat16_rn(v.w); f = v.w - __bfloat162float(b); h.w = __bfloat16_as_ushort(b); l.w = __bfloat16_as_ushort(__float2bfloat16_rn(f));
    ((ushort4*)g_Ah)[i] = h;
    ((ushort4*)g_Al)[i] = l;
}

__global__ void k_splitW(const float* __restrict__ W, int K, int N) {
    int i = blockIdx.x * blockDim.x + threadIdx.x;
    if (i >= N * K) return;
    int n = i / K, k = i % K;
    float v = W[(size_t)k * N + n];
    __nv_bfloat16 hi = __float2bfloat16_rn(v);
    g_Bh[i] = hi;
    g_Bl[i] = __float2bfloat16_rn(v - __bfloat162float(hi));
}

__global__ void k_splitWp(const float* __restrict__ Wp1) {
    int i = blockIdx.x * blockDim.x + threadIdx.x;
    if (i >= 128 * 256) return;
    int n = i / 256, k = i % 256;
    float v = 0.f;
    if (n < 32)      v = Wp1[(size_t)k * 32 + n];
    else if (n < 64) v = Wp1[(size_t)(256 + k) * 32 + (n - 32)];
    __nv_bfloat16 hi = __float2bfloat16_rn(v);
    g_Bh[i] = hi;
    g_Bl[i] = __float2bfloat16_rn(v - __bfloat162float(hi));
}

// ---------------- mma.sync split-bf16 GEMM with cp.async double buffer ----------------
static constexpr int PADK = 40;
static constexpr int TSZ  = 128 * PADK;                 // uint16 per array
static constexpr int MMASMEM = 2 * 4 * TSZ * 2;         // bytes (81920)

__global__ __launch_bounds__(256) void k_mma(const __nv_bfloat16* __restrict__ Ah,
                                             const __nv_bfloat16* __restrict__ Al,
                                             const __nv_bfloat16* __restrict__ Bh,
                                             const __nv_bfloat16* __restrict__ Bl,
                                             float* __restrict__ C,
                                             int M, int Nstore, int K, int ldc) {
    extern __shared__ __align__(16) uint16_t sm[];

    int tid = threadIdx.x, lane = tid & 31, wid = tid >> 5;
    int wm = wid & 1, wn = wid >> 1;
    int bm = blockIdx.y * 128, bn = blockIdx.x * 128;

    float acc[4][4][4];
    #pragma unroll
    for (int mi = 0; mi < 4; mi++)
        #pragma unroll
        for (int ni = 0; ni < 4; ni++)
            #pragma unroll
            for (int j = 0; j < 4; j++) acc[mi][ni][j] = 0.f;

    int nk = K >> 5;

    auto issue = [&](int kc, int st) {
        int k0 = kc << 5;
        uint16_t* tA0 = sm + (st * 4 + 0) * TSZ;
        uint16_t* tA1 = sm + (st * 4 + 1) * TSZ;
        uint16_t* tB0 = sm + (st * 4 + 2) * TSZ;
        uint16_t* tB1 = sm + (st * 4 + 3) * TSZ;
        #pragma unroll
        for (int t = 0; t < 2; t++) {
            int u = tid + t * 256;
            int r = u >> 2, c8 = (u & 3) * 8;
            size_t ga = (size_t)(bm + r) * K + k0 + c8;
            size_t gb = (size_t)(bn + r) * K + k0 + c8;
            cpasync16(tA0 + r * PADK + c8, Ah + ga);
            cpasync16(tA1 + r * PADK + c8, Al + ga);
            cpasync16(tB0 + r * PADK + c8, Bh + gb);
            cpasync16(tB1 + r * PADK + c8, Bl + gb);
        }
        asm volatile("cp.async.commit_group;" ::: "memory");
    };

    issue(0, 0);
    for (int kc = 0; kc < nk; kc++) {
        int st = kc & 1;
        if (kc + 1 < nk) {
            issue(kc + 1, st ^ 1);
            asm volatile("cp.async.wait_group 1;" ::: "memory");
        } else {
            asm volatile("cp.async.wait_group 0;" ::: "memory");
        }
        __syncthreads();

        uint16_t* sAh = sm + (st * 4 + 0) * TSZ;
        uint16_t* sAl = sm + (st * 4 + 1) * TSZ;
        uint16_t* sBh = sm + (st * 4 + 2) * TSZ;
        uint16_t* sBl = sm + (st * 4 + 3) * TSZ;

        #pragma unroll
        for (int ks = 0; ks < 2; ks++) {
            int kb = ks * 16;
            uint32_t ah[4][4], al[4][4], bh[4][2], bl[4][2];
            #pragma unroll
            for (int mi = 0; mi < 4; mi++) {
                int row = wm * 64 + mi * 16 + (lane & 15);
                int kc2 = kb + (lane >> 4) * 8;
                ldsm4(ah[mi], smem_u32(&sAh[row * PADK + kc2]));
                ldsm4(al[mi], smem_u32(&sAl[row * PADK + kc2]));
            }
            #pragma unroll
            for (int g = 0; g < 2; g++) {
                int tI = lane >> 3;
                int nrow = wn * 32 + g * 16 + (tI >> 1) * 8 + (lane & 7);
                int kc2  = kb + (tI & 1) * 8;
                uint32_t r4[4];
                ldsm4(r4, smem_u32(&sBh[nrow * PADK + kc2]));
                bh[g * 2][0] = r4[0]; bh[g * 2][1] = r4[1];
                bh[g * 2 + 1][0] = r4[2]; bh[g * 2 + 1][1] = r4[3];
                ldsm4(r4, smem_u32(&sBl[nrow * PADK + kc2]));
                bl[g * 2][0] = r4[0]; bl[g * 2][1] = r4[1];
                bl[g * 2 + 1][0] = r4[2]; bl[g * 2 + 1][1] = r4[3];
            }
            #pragma unroll
            for (int mi = 0; mi < 4; mi++)
                #pragma unroll
                for (int ni = 0; ni < 4; ni++) {
                    mma16816(acc[mi][ni], ah[mi], bh[ni]);
                    mma16816(acc[mi][ni], ah[mi], bl[ni]);
                    mma16816(acc[mi][ni], al[mi], bh[ni]);
                }
        }
        __syncthreads();
    }

    #pragma unroll
    for (int mi = 0; mi < 4; mi++) {
        int m0 = bm + wm * 64 + mi * 16 + (lane >> 2);
        #pragma unroll
        for (int ni = 0; ni < 4; ni++) {
            int c0 = bn + wn * 32 + ni * 8 + (lane & 3) * 2;
            if (c0 < Nstore) {
                if (m0 < M)
                    *(float2*)&C[(size_t)m0 * ldc + c0] =
                        make_float2(acc[mi][ni][0], acc[mi][ni][1]);
                if (m0 + 8 < M)
                    *(float2*)&C[(size_t)(m0 + 8) * ldc + c0] =
                        make_float2(acc[mi][ni][2], acc[mi][ni][3]);
            }
        }
    }
}

// ---------------- attention coefficients ----------------
__global__ void k_attn(const float* __restrict__ h, const float* __restrict__ a_src,
                       const float* __restrict__ a_dst) {
    int warp = (blockIdx.x * blockDim.x + threadIdx.x) >> 5;
    int lane = threadIdx.x & 31;
    if (warp >= NN) return;
    int head = lane >> 2, part = lane & 3;
    const float4* hp = (const float4*)(h + (size_t)warp * F + head * 32 + part * 8);
    const float4* ap = (const float4*)(a_src + head * 32 + part * 8);
    const float4* dp = (const float4*)(a_dst + head * 32 + part * 8);
    float4 h0 = hp[0], h1 = hp[1];
    float4 a0 = ap[0], a1 = ap[1];
    float4 d0 = dp[0], d1 = dp[1];
    float s = h0.x * a0.x + h0.y * a0.y + h0.z * a0.z + h0.w * a0.w
            + h1.x * a1.x + h1.y * a1.y + h1.z * a1.z + h1.w * a1.w;
    float d = h0.x * d0.x + h0.y * d0.y + h0.z * d0.z + h0.w * d0.w
            + h1.x * d1.x + h1.y * d1.y + h1.z * d1.z + h1.w * d1.w;
    s += __shfl_xor_sync(FULL, s, 1); s += __shfl_xor_sync(FULL, s, 2);
    d += __shfl_xor_sync(FULL, d, 1); d += __shfl_xor_sync(FULL, d, 2);
    if (part == 0) {
        g_as[warp * HEADS + head] = s;
        g_ad[warp * HEADS + head] = d;
    }
}

// ---------------- GAT aggregation: online softmax + FFMA2, bf16 hi/lo epilogue ----------------
__global__ void k_agg(const float* __restrict__ h, const float* __restrict__ bias) {
    int n = (blockIdx.x * blockDim.x + threadIdx.x) >> 5;
    int lane = threadIdx.x & 31;
    if (n >= NN) return;
    int head = lane >> 2, part = lane & 3;

    float adv = g_ad[n * HEADS + head];
    float m = lrelu(g_as[n * HEADS + head] + adv);   // e_self
    float denom = 1.f;
    int beg = g_off[n], end = g_off[n + 1];

    const float4* hp = (const float4*)(h + (size_t)n * F + head * 32 + part * 8);
    float4 v0 = hp[0], v1 = hp[1];
    float2 acc[4] = { {v0.x, v0.y}, {v0.z, v0.w}, {v1.x, v1.y}, {v1.z, v1.w} };

    for (int i = beg; i < end; i++) {
        int s = g_col[i];
        float e = lrelu(g_as[s * HEADS + head] + adv);
        const float4* sp = (const float4*)(h + (size_t)s * F + head * 32 + part * 8);
        float4 s0 = sp[0], s1 = sp[1];
        float2 p0 = {s0.x, s0.y}, p1 = {s0.z, s0.w}, p2 = {s1.x, s1.y}, p3 = {s1.z, s1.w};
        if (e > m) {
            float r = __expf(m - e);
            denom = fmaf(denom, r, 1.f);
            float2 rr = {r, r};
            ffma2(p0, acc[0], rr); acc[0] = p0;
            ffma2(p1, acc[1], rr); acc[1] = p1;
            ffma2(p2, acc[2], rr); acc[2] = p2;
            ffma2(p3, acc[3], rr); acc[3] = p3;
            m = e;
        } else {
            float w = __expf(e - m);
            denom += w;
            float2 ww = {w, w};
            ffma2(acc[0], p0, ww);
            ffma2(acc[1], p1, ww);
            ffma2(acc[2], p2, ww);
            ffma2(acc[3], p3, ww);
        }
    }
    float inv = 1.f / denom;
    const float4* bp = (const float4*)(bias + head * 32 + part * 8);
    float4 b0 = bp[0], b1 = bp[1];
    float o[8];
    o[0] = fmaxf(fmaf(acc[0].x, inv, b0.x), 0.f);
    o[1] = fmaxf(fmaf(acc[0].y, inv, b0.y), 0.f);
    o[2] = fmaxf(fmaf(acc[1].x, inv, b0.z), 0.f);
    o[3] = fmaxf(fmaf(acc[1].y, inv, b0.w), 0.f);
    o[4] = fmaxf(fmaf(acc[2].x, inv, b1.x), 0.f);
    o[5] = fmaxf(fmaf(acc[2].y, inv, b1.y), 0.f);
    o[6] = fmaxf(fmaf(acc[3].x, inv, b1.z), 0.f);
    o[7] = fmaxf(fmaf(acc[3].y, inv, b1.w), 0.f);

    ushort4 hA, hB, lA, lB;
    {
        __nv_bfloat16 b;
        float f;
        b = __float2bfloat16_rn(o[0]); f = o[0] - __bfloat162float(b); hA.x = __bfloat16_as_ushort(b); lA.x = __bfloat16_as_ushort(__float2bfloat16_rn(f));
        b = __float2bfloat16_rn(o[1]); f = o[1] - __bfloat162float(b); hA.y = __bfloat16_as_ushort(b); lA.y = __bfloat16_as_ushort(__float2bfloat16_rn(f));
        b = __float2bfloat16_rn(o[2]); f = o[2] - __bfloat162float(b); hA.z = __bfloat16_as_ushort(b); lA.z = __bfloat16_as_ushort(__float2bfloat16_rn(f));
        b = __float2bfloat16_rn(o[3]); f = o[3] - __bfloat162float(b); hA.w = __bfloat16_as_ushort(b); lA.w = __bfloat16_as_ushort(__float2bfloat16_rn(f));
        b = __float2bfloat16_rn(o[4]); f = o[4] - __bfloat162float(b); hB.x = __bfloat16_as_ushort(b); lB.x = __bfloat16_as_ushort(__float2bfloat16_rn(f));
        b = __float2bfloat16_rn(o[5]); f = o[5] - __bfloat162float(b); hB.y = __bfloat16_as_ushort(b); lB.y = __bfloat16_as_ushort(__float2bfloat16_rn(f));
        b = __float2bfloat16_rn(o[6]); f = o[6] - __bfloat162float(b); hB.z = __bfloat16_as_ushort(b); lB.z = __bfloat16_as_ushort(__float2bfloat16_rn(f));
        b = __float2bfloat16_rn(o[7]); f = o[7] - __bfloat162float(b); hB.w = __bfloat16_as_ushort(b); lB.w = __bfloat16_as_ushort(__float2bfloat16_rn(f));
    }
    size_t off = (size_t)n * 256 + head * 32 + part * 8;
    *(ushort4*)(g_Ah + off)     = hA;
    *(ushort4*)(g_Ah + off + 4) = hB;
    *(ushort4*)(g_Al + off)     = lA;
    *(ushort4*)(g_Al + off + 4) = lB;
}

// ---------------- edge predictor: 2 edges per thread, FFMA2 inner loop ----------------
__global__ __launch_bounds__(128) void k_pred(const int* __restrict__ EI,
                                              const float* __restrict__ EA,
                                              const float* __restrict__ Wm1,
                                              const float* __restrict__ bm1,
                                              const float* __restrict__ Wm2,
                                              const float* __restrict__ bm2,
                                              const float* __restrict__ Wp1,
                                              const float* __restrict__ bp1,
                                              const float* __restrict__ Wp2,
                                              const float* __restrict__ bp2,
                                              float* __restrict__ OUT) {
    __shared__ float sW[3 * 1024];
    __shared__ float sB[3 * 32];
    __shared__ float sWp2[32];
    __shared__ float sbp2;

    int tid = threadIdx.x;
    for (int i = tid; i < 1024; i += 128) {
        sW[i]        = Wm1[i];
        sW[1024 + i] = Wm2[i];
        sW[2048 + i] = Wp1[512 * 32 + i];
    }
    if (tid < 32) {
        sB[tid]      = bm1[tid];
        sB[32 + tid] = bm2[tid];
        sB[64 + tid] = bp1[tid];
        sWp2[tid]    = Wp2[tid];
    }
    if (tid == 0) sbp2 = bp2[0];
    __syncthreads();

    int e0 = blockIdx.x * 256 + tid;
    int e1 = e0 + 128;
    if (e0 >= NE) return;
    bool has1 = (e1 < NE);
    int e1c = has1 ? e1 : e0;

    int r0 = EI[e0], c0 = EI[NE + e0];
    int r1 = EI[e1c], c1 = EI[NE + e1c];

    float in0[32], in1[32];
    {
        const float4* p0 = (const float4*)(EA + (size_t)e0 * 32);
        const float4* p1 = (const float4*)(EA + (size_t)e1c * 32);
        #pragma unroll
        for (int q = 0; q < 8; q++) {
            float4 v = p0[q];
            in0[q * 4 + 0] = v.x; in0[q * 4 + 1] = v.y;
            in0[q * 4 + 2] = v.z; in0[q * 4 + 3] = v.w;
            float4 u = p1[q];
            in1[q * 4 + 0] = u.x; in1[q * 4 + 1] = u.y;
            in1[q * 4 + 2] = u.z; in1[q * 4 + 3] = u.w;
        }
    }

    const float2* pa0 = (const float2*)(g_P + (size_t)r0 * 64);
    const float2* pb0 = (const float2*)(g_P + (size_t)c0 * 64 + 32);
    const float2* pa1 = (const float2*)(g_P + (size_t)r1 * 64);
    const float2* pb1 = (const float2*)(g_P + (size_t)c1 * 64 + 32);

    #pragma unroll 1
    for (int L = 0; L < 3; L++) {
        const float2* w2 = (const float2*)(sW + L * 1024);   // [k][16 float2]
        const float2* b2 = (const float2*)(sB + L * 32);     // 16 float2
        float2 aA[16], aB[16];                               // edge0 / edge1, pairs
        #pragma unroll
        for (int j = 0; j < 16; j++) { aA[j] = b2[j]; aB[j] = b2[j]; }
        if (L == 2) {
            #pragma unroll
            for (int j = 0; j < 16; j++) {
                float2 x = pa0[j], y = pb0[j];
                aA[j].x += x.x + y.x; aA[j].y += x.y + y.y;
                float2 u = pa1[j], v = pb1[j];
                aB[j].x += u.x + v.x; aB[j].y += u.y + v.y;
            }
        }
        #pragma unroll
        for (int k = 0; k < 32; k++) {
            float2 v0 = {in0[k], in0[k]};
            float2 v1 = {in1[k], in1[k]};
            #pragma unroll
            for (int j = 0; j < 16; j++) {
                float2 w = w2[k * 16 + j];
                ffma2(aA[j], v0, w);
                ffma2(aB[j], v1, w);
            }
        }
        #pragma unroll
        for (int j = 0; j < 16; j++) {
            in0[j * 2 + 0] = fmaxf(aA[j].x, 0.f);
            in0[j * 2 + 1] = fmaxf(aA[j].y, 0.f);
            in1[j * 2 + 0] = fmaxf(aB[j].x, 0.f);
            in1[j * 2 + 1] = fmaxf(aB[j].y, 0.f);
        }
    }

    float s0 = sbp2, s1 = sbp2;
    #pragma unroll
    for (int j = 0; j < 32; j++) {
        float w = sWp2[j];
        s0 = fmaf(in0[j], w, s0);
        s1 = fmaf(in1[j], w, s1);
    }
    OUT[e0] = s0;
    if (has1) OUT[e1] = s1;
}

// ---------------- launch ----------------
extern "C" void kernel_launch(void* const* d_in, const int* in_sizes, int n_in,
                              void* d_out, int out_size) {
    const float* x    = (const float*)d_in[0];
    const int*   ei   = (const int*)d_in[1];
    const float* ea   = (const float*)d_in[2];
    const float* W1   = (const float*)d_in[3];
    const float* as1  = (const float*)d_in[4];
    const float* ad1  = (const float*)d_in[5];
    const float* b1   = (const float*)d_in[6];
    const float* W2   = (const float*)d_in[7];
    const float* as2  = (const float*)d_in[8];
    const float* ad2  = (const float*)d_in[9];
    const float* b2   = (const float*)d_in[10];
    const float* Wm1  = (const float*)d_in[11];
    const float* bm1  = (const float*)d_in[12];
    const float* Wm2  = (const float*)d_in[13];
    const float* bm2  = (const float*)d_in[14];
    const float* Wp1  = (const float*)d_in[15];
    const float* bp1  = (const float*)d_in[16];
    const float* Wp2  = (const float*)d_in[17];
    const float* bp2  = (const float*)d_in[18];
    float* out = (float*)d_out;

    float *ph, *pP;
    __nv_bfloat16 *pAh, *pAl, *pBh, *pBl;
    cudaGetSymbolAddress((void**)&ph,  g_h);
    cudaGetSymbolAddress((void**)&pP,  g_P);
    cudaGetSymbolAddress((void**)&pAh, g_Ah);
    cudaGetSymbolAddress((void**)&pAl, g_Al);
    cudaGetSymbolAddress((void**)&pBh, g_Bh);
    cudaGetSymbolAddress((void**)&pBl, g_Bl);

    cudaFuncSetAttribute(k_mma, cudaFuncAttributeMaxDynamicSharedMemorySize, MMASMEM);

    // CSR
    {
        int* degp; cudaGetSymbolAddress((void**)&degp, g_deg);
        k_zero<<<(NN + 255) / 256, 256>>>(degp, NN);
    }
    k_count<<<(NE + 255) / 256, 256>>>(ei);
    k_scan<<<1, 1024>>>();
    k_fill<<<(NE + 255) / 256, 256>>>(ei);

    int nwBlocks = (NN * 32 + 255) / 256;
    int tilesM = MPAD / 128;   // 391

    // ---- layer 1:  h = x @ W1 ----
    k_splitW<<<(256 * NODE_IN + 255) / 256, 256>>>(W1, NODE_IN, F);
    {
        int t4 = NN * NODE_IN / 4;
        k_splitA<<<(t4 + 255) / 256, 256>>>(x, t4);
    }
    k_mma<<<dim3(2, tilesM), 256, MMASMEM>>>(pAh, pAl, pBh, pBl, ph, NN, F, NODE_IN, F);
    k_attn<<<nwBlocks, 256>>>(ph, as1, ad1);
    k_agg<<<nwBlocks, 256>>>(ph, b1);   // writes g_Ah/g_Al (layer-2 A operand)

    // ---- layer 2:  h = x @ W2 ----
    k_splitW<<<(256 * 256 + 255) / 256, 256>>>(W2, F, F);
    k_mma<<<dim3(2, tilesM), 256, MMASMEM>>>(pAh, pAl, pBh, pBl, ph, NN, F, F, F);
    k_attn<<<nwBlocks, 256>>>(ph, as2, ad2);
    k_agg<<<nwBlocks, 256>>>(ph, b2);   // writes g_Ah/g_Al (P-GEMM A operand)

    // ---- node-side predictor partials: P = x @ [Wp1_a | Wp1_b] ----
    k_splitWp<<<(128 * 256 + 255) / 256, 256>>>(Wp1);
    k_mma<<<dim3(1, tilesM), 256, MMASMEM>>>(pAh, pAl, pBh, pBl, pP, NN, 64, F, 64);

    // ---- edge predictor ----
    k_pred<<<(NE + 255) / 256, 128>>>(ei, ea, Wm1, bm1, Wm2, bm2,
                                      Wp1, bp1, Wp2, bp2, out);
}

// round 12
// speedup vs baseline: 1.0426x; 1.0426x over previous
#include <cuda_runtime.h>
#include <cuda_bf16.h>
#include <cstdint>

#define FULL 0xffffffffu

static constexpr int NN      = 50000;
static constexpr int NE      = 400000;
static constexpr int NODE_IN = 128;
static constexpr int F       = 256;   // HEADS*HID
static constexpr int HEADS   = 8;
static constexpr float SLOPE = 0.2f;
static constexpr int MPAD    = 50048; // 391 * 128

// ---------------- scratch (device globals; no allocation allowed) ----------------
__device__ float g_h[(size_t)NN * F];   // pre-aggregation node features
__device__ float g_P[(size_t)NN * 64];  // per-node predictor partials [Pa|Pb]
__device__ __nv_bfloat16 g_Ah[(size_t)MPAD * 256];
__device__ __nv_bfloat16 g_Al[(size_t)MPAD * 256];
__device__ __nv_bfloat16 g_B1h[256 * 128];
__device__ __nv_bfloat16 g_B1l[256 * 128];
__device__ __nv_bfloat16 g_B2h[256 * 256];
__device__ __nv_bfloat16 g_B2l[256 * 256];
__device__ __nv_bfloat16 g_Bph[128 * 256];
__device__ __nv_bfloat16 g_Bpl[128 * 256];
__device__ float g_as[NN * HEADS];
__device__ float g_ad[NN * HEADS];
__device__ int   g_deg[NN];
__device__ int   g_off[NN + 1];
__device__ int   g_cur[NN];
__device__ int   g_col[NE];

__device__ __forceinline__ float lrelu(float x) { return x > 0.f ? x : SLOPE * x; }

__device__ __forceinline__ uint32_t smem_u32(const void* p) {
    uint32_t a;
    asm("{ .reg .u64 t; cvta.to.shared.u64 t, %1; cvt.u32.u64 %0, t; }" : "=r"(a) : "l"(p));
    return a;
}
__device__ __forceinline__ void ldsm4(uint32_t* r, uint32_t addr) {
    asm volatile("ldmatrix.sync.aligned.m8n8.x4.shared.b16 {%0,%1,%2,%3}, [%4];"
                 : "=r"(r[0]), "=r"(r[1]), "=r"(r[2]), "=r"(r[3]) : "r"(addr));
}
__device__ __forceinline__ void mma16816(float* c, const uint32_t* a, const uint32_t* b) {
    asm volatile("mma.sync.aligned.m16n8k16.row.col.f32.bf16.bf16.f32 "
                 "{%0,%1,%2,%3}, {%4,%5,%6,%7}, {%8,%9}, {%0,%1,%2,%3};"
                 : "+f"(c[0]), "+f"(c[1]), "+f"(c[2]), "+f"(c[3])
                 : "r"(a[0]), "r"(a[1]), "r"(a[2]), "r"(a[3]), "r"(b[0]), "r"(b[1]));
}
// packed c = a*b + c  (FFMA2; sm_100+)
__device__ __forceinline__ void ffma2(float2& c, float2 a, float2 b) {
    unsigned long long cc, aa, bb;
    cc = *reinterpret_cast<unsigned long long*>(&c);
    aa = *reinterpret_cast<unsigned long long*>(&a);
    bb = *reinterpret_cast<unsigned long long*>(&b);
    asm("fma.rn.f32x2 %0, %1, %2, %0;" : "+l"(cc) : "l"(aa), "l"(bb));
    *reinterpret_cast<unsigned long long*>(&c) = cc;
}
__device__ __forceinline__ void cpasync16(void* dst, const void* src) {
    asm volatile("cp.async.ca.shared.global [%0], [%1], 16;"
                 :: "r"(smem_u32(dst)), "l"(src));
}
__device__ __forceinline__ void splitStore(__nv_bfloat16* H, __nv_bfloat16* L, int i, float v) {
    __nv_bfloat16 hi = __float2bfloat16_rn(v);
    H[i] = hi;
    L[i] = __float2bfloat16_rn(v - __bfloat162float(hi));
}

// ---------------- CSR pieces ----------------
__global__ void k_zero(int* p, int n) {
    int i = blockIdx.x * blockDim.x + threadIdx.x;
    if (i < n) p[i] = 0;
}
__global__ void k_scan() {
    __shared__ int sh[32];
    __shared__ int s_carry;
    int tid = threadIdx.x;
    if (tid == 0) s_carry = 0;
    __syncthreads();
    for (int base = 0; base < NN; base += 1024) {
        int v = (base + tid < NN) ? g_deg[base + tid] : 0;
        int x = v;
        #pragma unroll
        for (int d = 1; d < 32; d <<= 1) {
            int y = __shfl_up_sync(FULL, x, d);
            if ((tid & 31) >= d) x += y;
        }
        if ((tid & 31) == 31) sh[tid >> 5] = x;
        __syncthreads();
        if (tid < 32) {
            int w = sh[tid];
            int wx = w;
            #pragma unroll
            for (int d = 1; d < 32; d <<= 1) {
                int y = __shfl_up_sync(FULL, wx, d);
                if (tid >= d) wx += y;
            }
            sh[tid] = wx - w;
        }
        __syncthreads();
        int incl = x + sh[tid >> 5];
        int excl = incl - v;
        int carry = s_carry;
        if (base + tid < NN) {
            g_off[base + tid] = carry + excl;
            g_cur[base + tid] = carry + excl;
        }
        __syncthreads();
        if (tid == 1023) s_carry = carry + incl;
        __syncthreads();
    }
    if (tid == 0) g_off[NN] = s_carry;
}
__global__ void k_fill(const int* __restrict__ ei) {
    int e = blockIdx.x * blockDim.x + threadIdx.x;
    if (e < NE) {
        int s = ei[e], d = ei[NE + e];
        int p = atomicAdd(&g_cur[d], 1);
        g_col[p] = s;
    }
}

// ---------------- fused prep: edge count + splitA(x) + all weight splits ----------------
// grid sections (256 thr): [0,1563) count | [1563,7813) splitA | [7813,7941) W1
//                          [7941,8197) W2 | [8197,8325) Wp
__global__ void k_prep(const int* __restrict__ ei, const float* __restrict__ x,
                       const float* __restrict__ W1, const float* __restrict__ W2,
                       const float* __restrict__ Wp1) {
    int b = blockIdx.x, tid = threadIdx.x;
    if (b < 1563) {
        int e = b * 256 + tid;
        if (e < NE) atomicAdd(&g_deg[ei[NE + e]], 1);
    } else if (b < 7813) {
        int i = (b - 1563) * 256 + tid;          // < 1,600,000 exactly
        float4 v = ((const float4*)x)[i];
        ushort4 h, l;
        float f;
        __nv_bfloat16 bb;
        bb = __float2bfloat16_rn(v.x); f = v.x - __bfloat162float(bb); h.x = __bfloat16_as_ushort(bb); l.x = __bfloat16_as_ushort(__float2bfloat16_rn(f));
        bb = __float2bfloat16_rn(v.y); f = v.y - __bfloat162float(bb); h.y = __bfloat16_as_ushort(bb); l.y = __bfloat16_as_ushort(__float2bfloat16_rn(f));
        bb = __float2bfloat16_rn(v.z); f = v.z - __bfloat162float(bb); h.z = __bfloat16_as_ushort(bb); l.z = __bfloat16_as_ushort(__float2bfloat16_rn(f));
        bb = __float2bfloat16_rn(v.w); f = v.w - __bfloat162float(bb); h.w = __bfloat16_as_ushort(bb); l.w = __bfloat16_as_ushort(__float2bfloat16_rn(f));
        ((ushort4*)g_Ah)[i] = h;
        ((ushort4*)g_Al)[i] = l;
    } else if (b < 7941) {
        int i = (b - 7813) * 256 + tid;          // W1 [128,256] -> [256][128]
        int n = i >> 7, k = i & 127;
        splitStore(g_B1h, g_B1l, i, W1[k * 256 + n]);
    } else if (b < 8197) {
        int i = (b - 7941) * 256 + tid;          // W2 [256,256] -> [256][256]
        int n = i >> 8, k = i & 255;
        splitStore(g_B2h, g_B2l, i, W2[k * 256 + n]);
    } else {
        int i = (b - 8197) * 256 + tid;          // Wp1 [544,32] -> [128][256] padded
        int n = i >> 8, k = i & 255;
        float v = 0.f;
        if (n < 32)      v = Wp1[k * 32 + n];
        else if (n < 64) v = Wp1[(256 + k) * 32 + (n - 32)];
        splitStore(g_Bph, g_Bpl, i, v);
    }
}

// ---------------- mma.sync split-bf16 GEMM + fused attention epilogue ----------------
static constexpr int PADK = 40;
static constexpr int TSZ  = 128 * PADK;
static constexpr int MMASMEM = 2 * 4 * TSZ * 2;   // 81920 bytes

__global__ __launch_bounds__(256) void k_mma(const __nv_bfloat16* __restrict__ Ah,
                                             const __nv_bfloat16* __restrict__ Al,
                                             const __nv_bfloat16* __restrict__ Bh,
                                             const __nv_bfloat16* __restrict__ Bl,
                                             float* __restrict__ C,
                                             const float* __restrict__ Asrc,
                                             const float* __restrict__ Adst,
                                             int M, int Nstore, int K, int ldc) {
    extern __shared__ __align__(16) uint16_t sm[];

    int tid = threadIdx.x, lane = tid & 31, wid = tid >> 5;
    int wm = wid & 1, wn = wid >> 1;
    int bm = blockIdx.y * 128, bn = blockIdx.x * 128;

    float acc[4][4][4];
    #pragma unroll
    for (int mi = 0; mi < 4; mi++)
        #pragma unroll
        for (int ni = 0; ni < 4; ni++)
            #pragma unroll
            for (int j = 0; j < 4; j++) acc[mi][ni][j] = 0.f;

    int nk = K >> 5;

    auto issue = [&](int kc, int st) {
        int k0 = kc << 5;
        uint16_t* tA0 = sm + (st * 4 + 0) * TSZ;
        uint16_t* tA1 = sm + (st * 4 + 1) * TSZ;
        uint16_t* tB0 = sm + (st * 4 + 2) * TSZ;
        uint16_t* tB1 = sm + (st * 4 + 3) * TSZ;
        #pragma unroll
        for (int t = 0; t < 2; t++) {
            int u = tid + t * 256;
            int r = u >> 2, c8 = (u & 3) * 8;
            size_t ga = (size_t)(bm + r) * K + k0 + c8;
            size_t gb = (size_t)(bn + r) * K + k0 + c8;
            cpasync16(tA0 + r * PADK + c8, Ah + ga);
            cpasync16(tA1 + r * PADK + c8, Al + ga);
            cpasync16(tB0 + r * PADK + c8, Bh + gb);
            cpasync16(tB1 + r * PADK + c8, Bl + gb);
        }
        asm volatile("cp.async.commit_group;" ::: "memory");
    };

    issue(0, 0);
    for (int kc = 0; kc < nk; kc++) {
        int st = kc & 1;
        if (kc + 1 < nk) {
            issue(kc + 1, st ^ 1);
            asm volatile("cp.async.wait_group 1;" ::: "memory");
        } else {
            asm volatile("cp.async.wait_group 0;" ::: "memory");
        }
        __syncthreads();

        uint16_t* sAh = sm + (st * 4 + 0) * TSZ;
        uint16_t* sAl = sm + (st * 4 + 1) * TSZ;
        uint16_t* sBh = sm + (st * 4 + 2) * TSZ;
        uint16_t* sBl = sm + (st * 4 + 3) * TSZ;

        #pragma unroll
        for (int ks = 0; ks < 2; ks++) {
            int kb = ks * 16;
            uint32_t ah[4][4], al[4][4], bh[4][2], bl[4][2];
            #pragma unroll
            for (int mi = 0; mi < 4; mi++) {
                int row = wm * 64 + mi * 16 + (lane & 15);
                int kc2 = kb + (lane >> 4) * 8;
                ldsm4(ah[mi], smem_u32(&sAh[row * PADK + kc2]));
                ldsm4(al[mi], smem_u32(&sAl[row * PADK + kc2]));
            }
            #pragma unroll
            for (int g = 0; g < 2; g++) {
                int tI = lane >> 3;
                int nrow = wn * 32 + g * 16 + (tI >> 1) * 8 + (lane & 7);
                int kc2  = kb + (tI & 1) * 8;
                uint32_t r4[4];
                ldsm4(r4, smem_u32(&sBh[nrow * PADK + kc2]));
                bh[g * 2][0] = r4[0]; bh[g * 2][1] = r4[1];
                bh[g * 2 + 1][0] = r4[2]; bh[g * 2 + 1][1] = r4[3];
                ldsm4(r4, smem_u32(&sBl[nrow * PADK + kc2]));
                bl[g * 2][0] = r4[0]; bl[g * 2][1] = r4[1];
                bl[g * 2 + 1][0] = r4[2]; bl[g * 2 + 1][1] = r4[3];
            }
            #pragma unroll
            for (int mi = 0; mi < 4; mi++)
                #pragma unroll
                for (int ni = 0; ni < 4; ni++) {
                    mma16816(acc[mi][ni], ah[mi], bh[ni]);
                    mma16816(acc[mi][ni], ah[mi], bl[ni]);
                    mma16816(acc[mi][ni], al[mi], bh[ni]);
                }
        }
        __syncthreads();
    }

    // store C
    #pragma unroll
    for (int mi = 0; mi < 4; mi++) {
        int m0 = bm + wm * 64 + mi * 16 + (lane >> 2);
        #pragma unroll
        for (int ni = 0; ni < 4; ni++) {
            int c0 = bn + wn * 32 + ni * 8 + (lane & 3) * 2;
            if (c0 < Nstore) {
                if (m0 < M)
                    *(float2*)&C[(size_t)m0 * ldc + c0] =
                        make_float2(acc[mi][ni][0], acc[mi][ni][1]);
                if (m0 + 8 < M)
                    *(float2*)&C[(size_t)(m0 + 8) * ldc + c0] =
                        make_float2(acc[mi][ni][2], acc[mi][ni][3]);
            }
        }
    }

    // fused attention coefficients: this warp's 32 cols = exactly one head
    if (Asrc != nullptr) {
        int hd = (bn + wn * 32) >> 5;
        float asv[4][2], adv[4][2];
        #pragma unroll
        for (int ni = 0; ni < 4; ni++) {
            int c = hd * 32 + ni * 8 + (lane & 3) * 2;
            asv[ni][0] = Asrc[c]; asv[ni][1] = Asrc[c + 1];
            adv[ni][0] = Adst[c]; adv[ni][1] = Adst[c + 1];
        }
        #pragma unroll
        for (int mi = 0; mi < 4; mi++) {
            float s0 = 0.f, s1 = 0.f, d0 = 0.f, d1 = 0.f;
            #pragma unroll
            for (int ni = 0; ni < 4; ni++) {
                s0 += acc[mi][ni][0] * asv[ni][0] + acc[mi][ni][1] * asv[ni][1];
                s1 += acc[mi][ni][2] * asv[ni][0] + acc[mi][ni][3] * asv[ni][1];
                d0 += acc[mi][ni][0] * adv[ni][0] + acc[mi][ni][1] * adv[ni][1];
                d1 += acc[mi][ni][2] * adv[ni][0] + acc[mi][ni][3] * adv[ni][1];
            }
            s0 += __shfl_xor_sync(FULL, s0, 1); s0 += __shfl_xor_sync(FULL, s0, 2);
            s1 += __shfl_xor_sync(FULL, s1, 1); s1 += __shfl_xor_sync(FULL, s1, 2);
            d0 += __shfl_xor_sync(FULL, d0, 1); d0 += __shfl_xor_sync(FULL, d0, 2);
            d1 += __shfl_xor_sync(FULL, d1, 1); d1 += __shfl_xor_sync(FULL, d1, 2);
            if ((lane & 3) == 0) {
                int m0 = bm + wm * 64 + mi * 16 + (lane >> 2);
                if (m0 < M)     { g_as[m0 * HEADS + hd] = s0; g_ad[m0 * HEADS + hd] = d0; }
                if (m0 + 8 < M) { g_as[(m0 + 8) * HEADS + hd] = s1; g_ad[(m0 + 8) * HEADS + hd] = d1; }
            }
        }
    }
}

// ---------------- GAT aggregation: online softmax + FFMA2, bf16 hi/lo epilogue ----------------
__global__ void k_agg(const float* __restrict__ h, const float* __restrict__ bias) {
    int n = (blockIdx.x * blockDim.x + threadIdx.x) >> 5;
    int lane = threadIdx.x & 31;
    if (n >= NN) return;
    int head = lane >> 2, part = lane & 3;

    float adv = g_ad[n * HEADS + head];
    float m = lrelu(g_as[n * HEADS + head] + adv);   // e_self
    float denom = 1.f;
    int beg = g_off[n], end = g_off[n + 1];

    const float4* hp = (const float4*)(h + (size_t)n * F + head * 32 + part * 8);
    float4 v0 = hp[0], v1 = hp[1];
    float2 acc[4] = { {v0.x, v0.y}, {v0.z, v0.w}, {v1.x, v1.y}, {v1.z, v1.w} };

    for (int i = beg; i < end; i++) {
        int s = g_col[i];
        float e = lrelu(g_as[s * HEADS + head] + adv);
        const float4* sp = (const float4*)(h + (size_t)s * F + head * 32 + part * 8);
        float4 s0 = sp[0], s1 = sp[1];
        float2 p0 = {s0.x, s0.y}, p1 = {s0.z, s0.w}, p2 = {s1.x, s1.y}, p3 = {s1.z, s1.w};
        if (e > m) {
            float r = __expf(m - e);
            denom = fmaf(denom, r, 1.f);
            float2 rr = {r, r};
            ffma2(p0, acc[0], rr); acc[0] = p0;
            ffma2(p1, acc[1], rr); acc[1] = p1;
            ffma2(p2, acc[2], rr); acc[2] = p2;
            ffma2(p3, acc[3], rr); acc[3] = p3;
            m = e;
        } else {
            float w = __expf(e - m);
            denom += w;
            float2 ww = {w, w};
            ffma2(acc[0], p0, ww);
            ffma2(acc[1], p1, ww);
            ffma2(acc[2], p2, ww);
            ffma2(acc[3], p3, ww);
        }
    }
    float inv = 1.f / denom;
    const float4* bp = (const float4*)(bias + head * 32 + part * 8);
    float4 b0 = bp[0], b1 = bp[1];
    float o[8];
    o[0] = fmaxf(fmaf(acc[0].x, inv, b0.x), 0.f);
    o[1] = fmaxf(fmaf(acc[0].y, inv, b0.y), 0.f);
    o[2] = fmaxf(fmaf(acc[1].x, inv, b0.z), 0.f);
    o[3] = fmaxf(fmaf(acc[1].y, inv, b0.w), 0.f);
    o[4] = fmaxf(fmaf(acc[2].x, inv, b1.x), 0.f);
    o[5] = fmaxf(fmaf(acc[2].y, inv, b1.y), 0.f);
    o[6] = fmaxf(fmaf(acc[3].x, inv, b1.z), 0.f);
    o[7] = fmaxf(fmaf(acc[3].y, inv, b1.w), 0.f);

    ushort4 hA, hB, lA, lB;
    {
        __nv_bfloat16 b;
        float f;
        b = __float2bfloat16_rn(o[0]); f = o[0] - __bfloat162float(b); hA.x = __bfloat16_as_ushort(b); lA.x = __bfloat16_as_ushort(__float2bfloat16_rn(f));
        b = __float2bfloat16_rn(o[1]); f = o[1] - __bfloat162float(b); hA.y = __bfloat16_as_ushort(b); lA.y = __bfloat16_as_ushort(__float2bfloat16_rn(f));
        b = __float2bfloat16_rn(o[2]); f = o[2] - __bfloat162float(b); hA.z = __bfloat16_as_ushort(b); lA.z = __bfloat16_as_ushort(__float2bfloat16_rn(f));
        b = __float2bfloat16_rn(o[3]); f = o[3] - __bfloat162float(b); hA.w = __bfloat16_as_ushort(b); lA.w = __bfloat16_as_ushort(__float2bfloat16_rn(f));
        b = __float2bfloat16_rn(o[4]); f = o[4] - __bfloat162float(b); hB.x = __bfloat16_as_ushort(b); lB.x = __bfloat16_as_ushort(__float2bfloat16_rn(f));
        b = __float2bfloat16_rn(o[5]); f = o[5] - __bfloat162float(b); hB.y = __bfloat16_as_ushort(b); lB.y = __bfloat16_as_ushort(__float2bfloat16_rn(f));
        b = __float2bfloat16_rn(o[6]); f = o[6] - __bfloat162float(b); hB.z = __bfloat16_as_ushort(b); lB.z = __bfloat16_as_ushort(__float2bfloat16_rn(f));
        b = __float2bfloat16_rn(o[7]); f = o[7] - __bfloat162float(b); hB.w = __bfloat16_as_ushort(b); lB.w = __bfloat16_as_ushort(__float2bfloat16_rn(f));
    }
    size_t off = (size_t)n * 256 + head * 32 + part * 8;
    *(ushort4*)(g_Ah + off)     = hA;
    *(ushort4*)(g_Ah + off + 4) = hB;
    *(ushort4*)(g_Al + off)     = lA;
    *(ushort4*)(g_Al + off + 4) = lB;
}

// ---------------- edge predictor: 2 edges per thread, FFMA2 inner loop ----------------
__global__ __launch_bounds__(128) void k_pred(const int* __restrict__ EI,
                                              const float* __restrict__ EA,
                                              const float* __restrict__ Wm1,
                                              const float* __restrict__ bm1,
                                              const float* __restrict__ Wm2,
                                              const float* __restrict__ bm2,
                                              const float* __restrict__ Wp1,
                                              const float* __restrict__ bp1,
                                              const float* __restrict__ Wp2,
                                              const float* __restrict__ bp2,
                                              float* __restrict__ OUT) {
    __shared__ float sW[3 * 1024];
    __shared__ float sB[3 * 32];
    __shared__ float sWp2[32];
    __shared__ float sbp2;

    int tid = threadIdx.x;
    for (int i = tid; i < 1024; i += 128) {
        sW[i]        = Wm1[i];
        sW[1024 + i] = Wm2[i];
        sW[2048 + i] = Wp1[512 * 32 + i];
    }
    if (tid < 32) {
        sB[tid]      = bm1[tid];
        sB[32 + tid] = bm2[tid];
        sB[64 + tid] = bp1[tid];
        sWp2[tid]    = Wp2[tid];
    }
    if (tid == 0) sbp2 = bp2[0];
    __syncthreads();

    int e0 = blockIdx.x * 256 + tid;
    int e1 = e0 + 128;
    if (e0 >= NE) return;
    bool has1 = (e1 < NE);
    int e1c = has1 ? e1 : e0;

    int r0 = EI[e0], c0 = EI[NE + e0];
    int r1 = EI[e1c], c1 = EI[NE + e1c];

    float in0[32], in1[32];
    {
        const float4* p0 = (const float4*)(EA + (size_t)e0 * 32);
        const float4* p1 = (const float4*)(EA + (size_t)e1c * 32);
        #pragma unroll
        for (int q = 0; q < 8; q++) {
            float4 v = p0[q];
            in0[q * 4 + 0] = v.x; in0[q * 4 + 1] = v.y;
            in0[q * 4 + 2] = v.z; in0[q * 4 + 3] = v.w;
            float4 u = p1[q];
            in1[q * 4 + 0] = u.x; in1[q * 4 + 1] = u.y;
            in1[q * 4 + 2] = u.z; in1[q * 4 + 3] = u.w;
        }
    }

    const float2* pa0 = (const float2*)(g_P + (size_t)r0 * 64);
    const float2* pb0 = (const float2*)(g_P + (size_t)c0 * 64 + 32);
    const float2* pa1 = (const float2*)(g_P + (size_t)r1 * 64);
    const float2* pb1 = (const float2*)(g_P + (size_t)c1 * 64 + 32);

    #pragma unroll 1
    for (int L = 0; L < 3; L++) {
        const float2* w2 = (const float2*)(sW + L * 1024);
        const float2* b2 = (const float2*)(sB + L * 32);
        float2 aA[16], aB[16];
        #pragma unroll
        for (int j = 0; j < 16; j++) { aA[j] = b2[j]; aB[j] = b2[j]; }
        if (L == 2) {
            #pragma unroll
            for (int j = 0; j < 16; j++) {
                float2 x = pa0[j], y = pb0[j];
                aA[j].x += x.x + y.x; aA[j].y += x.y + y.y;
                float2 u = pa1[j], v = pb1[j];
                aB[j].x += u.x + v.x; aB[j].y += u.y + v.y;
            }
        }
        #pragma unroll
        for (int k = 0; k < 32; k++) {
            float2 v0 = {in0[k], in0[k]};
            float2 v1 = {in1[k], in1[k]};
            #pragma unroll
            for (int j = 0; j < 16; j++) {
                float2 w = w2[k * 16 + j];
                ffma2(aA[j], v0, w);
                ffma2(aB[j], v1, w);
            }
        }
        #pragma unroll
        for (int j = 0; j < 16; j++) {
            in0[j * 2 + 0] = fmaxf(aA[j].x, 0.f);
            in0[j * 2 + 1] = fmaxf(aA[j].y, 0.f);
            in1[j * 2 + 0] = fmaxf(aB[j].x, 0.f);
            in1[j * 2 + 1] = fmaxf(aB[j].y, 0.f);
        }
    }

    float s0 = sbp2, s1 = sbp2;
    #pragma unroll
    for (int j = 0; j < 32; j++) {
        float w = sWp2[j];
        s0 = fmaf(in0[j], w, s0);
        s1 = fmaf(in1[j], w, s1);
    }
    OUT[e0] = s0;
    if (has1) OUT[e1] = s1;
}

// ---------------- launch ----------------
extern "C" void kernel_launch(void* const* d_in, const int* in_sizes, int n_in,
                              void* d_out, int out_size) {
    const float* x    = (const float*)d_in[0];
    const int*   ei   = (const int*)d_in[1];
    const float* ea   = (const float*)d_in[2];
    const float* W1   = (const float*)d_in[3];
    const float* as1  = (const float*)d_in[4];
    const float* ad1  = (const float*)d_in[5];
    const float* b1   = (const float*)d_in[6];
    const float* W2   = (const float*)d_in[7];
    const float* as2  = (const float*)d_in[8];
    const float* ad2  = (const float*)d_in[9];
    const float* b2   = (const float*)d_in[10];
    const float* Wm1  = (const float*)d_in[11];
    const float* bm1  = (const float*)d_in[12];
    const float* Wm2  = (const float*)d_in[13];
    const float* bm2  = (const float*)d_in[14];
    const float* Wp1  = (const float*)d_in[15];
    const float* bp1  = (const float*)d_in[16];
    const float* Wp2  = (const float*)d_in[17];
    const float* bp2  = (const float*)d_in[18];
    float* out = (float*)d_out;

    float *ph, *pP;
    __nv_bfloat16 *pAh, *pAl, *pB1h, *pB1l, *pB2h, *pB2l, *pBph, *pBpl;
    cudaGetSymbolAddress((void**)&ph,   g_h);
    cudaGetSymbolAddress((void**)&pP,   g_P);
    cudaGetSymbolAddress((void**)&pAh,  g_Ah);
    cudaGetSymbolAddress((void**)&pAl,  g_Al);
    cudaGetSymbolAddress((void**)&pB1h, g_B1h);
    cudaGetSymbolAddress((void**)&pB1l, g_B1l);
    cudaGetSymbolAddress((void**)&pB2h, g_B2h);
    cudaGetSymbolAddress((void**)&pB2l, g_B2l);
    cudaGetSymbolAddress((void**)&pBph, g_Bph);
    cudaGetSymbolAddress((void**)&pBpl, g_Bpl);

    cudaFuncSetAttribute(k_mma, cudaFuncAttributeMaxDynamicSharedMemorySize, MMASMEM);

    int nwBlocks = (NN * 32 + 255) / 256;
    int tilesM = MPAD / 128;   // 391

    // 1. zero degree counters
    {
        int* degp; cudaGetSymbolAddress((void**)&degp, g_deg);
        k_zero<<<(NN + 255) / 256, 256>>>(degp, NN);
    }
    // 2. fused prep: count + splitA(x) + W1/W2/Wp splits (all independent, concurrent)
    k_prep<<<8325, 256>>>(ei, x, W1, W2, Wp1);
    // 3-4. CSR
    k_scan<<<1, 1024>>>();
    k_fill<<<(NE + 255) / 256, 256>>>(ei);

    // 5. layer 1 GEMM + fused attn coefficients
    k_mma<<<dim3(2, tilesM), 256, MMASMEM>>>(pAh, pAl, pB1h, pB1l, ph, as1, ad1, NN, F, NODE_IN, F);
    // 6. aggregate (writes split-bf16 A for layer 2)
    k_agg<<<nwBlocks, 256>>>(ph, b1);

    // 7. layer 2 GEMM + fused attn coefficients
    k_mma<<<dim3(2, tilesM), 256, MMASMEM>>>(pAh, pAl, pB2h, pB2l, ph, as2, ad2, NN, F, F, F);
    // 8. aggregate
    k_agg<<<nwBlocks, 256>>>(ph, b2);

    // 9. P = x @ [Wp1_a | Wp1_b]  (no attn)
    k_mma<<<dim3(1, tilesM), 256, MMASMEM>>>(pAh, pAl, pBph, pBpl, pP, nullptr, nullptr, NN, 64, F, 64);

    // 10. edge predictor
    k_pred<<<(NE + 255) / 256, 128>>>(ei, ea, Wm1, bm1, Wm2, bm2,
                                      Wp1, bp1, Wp2, bp2, out);
}